// round 15
// baseline (speedup 1.0000x reference)
#include <cuda_runtime.h>

// ---------------------------------------------------------------------------
// SSIM loss, fused single-pass implementation.
// imgs: (16,3,512,512) fp32 -> 48 independent 512x512 planes.
// 11x11 gaussian (sigma=1.5) is separable; same kernel for all 5 convs.
// Zero padding (pad=5) matches jax conv_general_dilated padding=((5,5),(5,5)).
// ---------------------------------------------------------------------------

#define TXW   128      // columns per block
#define HBK   64       // output rows per block
#define RING  20       // ring slots (window span 14 + 4 new writes <= 17, 20 safe)
#define WIMG  512
#define NPLANE 48

#define C1F 0.0001f    // 0.01^2
#define C2F 0.0009f    // 0.03^2

// normalized gaussian, sigma=1.5, 11 taps (computed in double, rounded to fp32)
__device__ __forceinline__ float gw(int k) {
    constexpr float G[11] = {
        0.00102838f, 0.00759876f, 0.03600077f, 0.10936069f, 0.21300553f,
        0.26601172f, 0.21300553f, 0.10936069f, 0.03600077f, 0.00759876f,
        0.00102838f
    };
    return G[k];
}

static __device__ double g_sum;

__global__ void ssim_zero_kernel() { g_sum = 0.0; }

__global__ void ssim_fin_kernel(float* out) {
    out[0] = (float)(1.0 - g_sum * (1.0 / 12582912.0)); // 48*512*512
}

// smem layout (floats):
//   ring[5][RING][TXW]            : 5*20*128 = 12800
//   inb [2][4][144]               : 1152      (row halo buffers, 138 used)
#define RING_FLOATS (5 * RING * TXW)
#define INB_FLOATS  (2 * 4 * 144)
#define SMEM_BYTES  ((RING_FLOATS + INB_FLOATS) * 4)

__global__ __launch_bounds__(128) void ssim_main_kernel(
    const float* __restrict__ img1, const float* __restrict__ img2)
{
    extern __shared__ float sm[];
    float* ring = sm;                  // [5][RING][TXW]
    float* inb  = sm + RING_FLOATS;    // [2][4][144]

    const int tid = threadIdx.x;
    const int b = blockIdx.x;
    const int plane = b >> 5;          // 32 blocks per plane (4 x-strips * 8 y-splits)
    const int t = b & 31;
    const int xbase = (t & 3) * TXW;
    const int yb    = (t >> 2) * HBK;

    const float* p1 = img1 + (size_t)plane * (WIMG * WIMG);
    const float* p2 = img2 + (size_t)plane * (WIMG * WIMG);

    // zero-init ring (keeps discarded-edge reads finite)
    for (int i = tid; i < RING_FLOATS; i += 128) ring[i] = 0.0f;

    // ---- precompute gmem load descriptors: 2 imgs * 4 rows * 138 cols = 1104 ----
    const int NLD = 9; // ceil(1104/128)
    const float* bptr[NLD];
    int   sofs[NLD];
    int   rowv[NLD];
    bool  act[NLD], cval[NLD];
#pragma unroll
    for (int m = 0; m < NLD; m++) {
        int idx = tid + m * 128;
        act[m] = (idx < 1104);
        int im = 0, row = 0, i = 0;
        if (act[m]) {
            im  = idx / 552;  int rem = idx - im * 552;
            row = rem / 138;  i = rem - row * 138;
        }
        int gc = xbase + i - 5;
        cval[m] = act[m] && (gc >= 0) && (gc < WIMG);
        rowv[m] = row;
        sofs[m] = im * (4 * 144) + row * 144 + i;
        const float* base = im ? p2 : p1;
        bptr[m] = base + row * WIMG + (cval[m] ? gc : 0);
    }

    const int hrow = tid >> 5;        // 0..3 (horizontal row within step)
    const int hcg  = tid & 31;        // column group
    const int hx0  = hcg << 2;

    float lsum = 0.0f;

    for (int s = 0; s < 20; ++s) {
        const int r0 = yb - 5 + 4 * s;     // absolute first input row this step

        if (s < 19) {
            // ---- load 4 input rows (with halo, zero-padded) into smem ----
            const long rbase = (long)r0 * WIMG;
#pragma unroll
            for (int m = 0; m < NLD; m++) {
                if (act[m]) {
                    int gr = r0 + rowv[m];
                    float v = 0.0f;
                    if (cval[m] && ((unsigned)gr < (unsigned)WIMG))
                        v = bptr[m][rbase];
                    inb[sofs[m]] = v;
                }
            }
            __syncthreads();

            // ---- horizontal conv: 4 output cols per thread, 1 row ----
            float a[16], bw[16];
            {
                const float4* pa = (const float4*)&inb[hrow * 144 + hx0];
                const float4* pb = (const float4*)&inb[4 * 144 + hrow * 144 + hx0];
#pragma unroll
                for (int m = 0; m < 4; m++) {
                    float4 va = pa[m];
                    a[4*m+0] = va.x; a[4*m+1] = va.y; a[4*m+2] = va.z; a[4*m+3] = va.w;
                    float4 vb = pb[m];
                    bw[4*m+0] = vb.x; bw[4*m+1] = vb.y; bw[4*m+2] = vb.z; bw[4*m+3] = vb.w;
                }
            }
            float acc[5][4];
#pragma unroll
            for (int q = 0; q < 5; q++)
#pragma unroll
                for (int j = 0; j < 4; j++) acc[q][j] = 0.0f;

#pragma unroll
            for (int pos = 0; pos < 14; pos++) {
                float av = a[pos], bv = bw[pos];
                float aa = av * av, b2 = bv * bv, ab = av * bv;
#pragma unroll
                for (int j = 0; j < 4; j++) {
                    int k = pos - j;
                    if (k >= 0 && k <= 10) {
                        float g = gw(k);
                        acc[0][j] = fmaf(av, g, acc[0][j]);
                        acc[1][j] = fmaf(bv, g, acc[1][j]);
                        acc[2][j] = fmaf(aa, g, acc[2][j]);
                        acc[3][j] = fmaf(b2, g, acc[3][j]);
                        acc[4][j] = fmaf(ab, g, acc[4][j]);
                    }
                }
            }
            int wslot = (4 * s + hrow) % RING;
#pragma unroll
            for (int q = 0; q < 5; q++) {
                *(float4*)&ring[(q * RING + wslot) * TXW + hx0] =
                    make_float4(acc[q][0], acc[q][1], acc[q][2], acc[q][3]);
            }
            __syncthreads();
        }

        // ---- vertical conv + SSIM: 1 column (tid), 4 output rows ----
        if (s >= 3) {
            const int wst = 4 * s - 13;             // window start, relative rows
            int slot0 = (wst + 2 * RING) % RING;
            int roff[14];
#pragma unroll
            for (int k = 0; k < 14; k++) {
                int sl = slot0 + k; if (sl >= RING) sl -= RING;
                roff[k] = sl * TXW + tid;
            }
            float sums[5][4];
#pragma unroll
            for (int q = 0; q < 5; q++) {
                const float* rq = ring + q * (RING * TXW);
                float w[14];
#pragma unroll
                for (int k = 0; k < 14; k++) w[k] = rq[roff[k]];
#pragma unroll
                for (int j = 0; j < 4; j++) {
                    float acc = 0.0f;
#pragma unroll
                    for (int k = 0; k < 11; k++) acc = fmaf(w[j + k], gw(k), acc);
                    sums[q][j] = acc;
                }
            }
#pragma unroll
            for (int j = 0; j < 4; j++) {
                int y = yb + wst + j;   // absolute output row
                if (y >= yb && y < yb + HBK) {
                    float mu1 = sums[0][j], mu2 = sums[1][j];
                    float x11 = sums[2][j], x22 = sums[3][j], x12 = sums[4][j];
                    float mu12 = mu1 * mu2;
                    float m1s = mu1 * mu1, m2s = mu2 * mu2;
                    float s1  = x11 - m1s;
                    float s2  = x22 - m2s;
                    float s12 = x12 - mu12;
                    float num = fmaf(2.0f, mu12, C1F) * fmaf(2.0f, s12, C2F);
                    float den = (m1s + m2s + C1F) * (s1 + s2 + C2F);
                    lsum += __fdividef(num, den);
                }
            }
        }
    }

    // ---- reduce: warp shfl -> smem -> one double atomic per block ----
#pragma unroll
    for (int o = 16; o; o >>= 1) lsum += __shfl_xor_sync(0xffffffffu, lsum, o);
    __shared__ float redbuf[4];
    if ((tid & 31) == 0) redbuf[tid >> 5] = lsum;
    __syncthreads();
    if (tid == 0) {
        float bs = redbuf[0] + redbuf[1] + redbuf[2] + redbuf[3];
        atomicAdd(&g_sum, (double)bs);
    }
}

extern "C" void kernel_launch(void* const* d_in, const int* in_sizes, int n_in,
                              void* d_out, int out_size)
{
    const float* img1 = (const float*)d_in[0];
    const float* img2 = (const float*)d_in[1];
    float* out = (float*)d_out;

    cudaFuncSetAttribute(ssim_main_kernel,
                         cudaFuncAttributeMaxDynamicSharedMemorySize, SMEM_BYTES);

    ssim_zero_kernel<<<1, 1>>>();
    ssim_main_kernel<<<NPLANE * 32, 128, SMEM_BYTES>>>(img1, img2);
    ssim_fin_kernel<<<1, 1>>>(out);
}

// round 16
// speedup vs baseline: 1.0031x; 1.0031x over previous
#include <cuda_runtime.h>

// ---------------------------------------------------------------------------
// SSIM loss, fused single-pass implementation.
// imgs: (16,3,512,512) fp32 -> 48 independent 512x512 planes.
// 11x11 gaussian (sigma=1.5) is separable; same kernel for all 5 convs.
// Zero padding (pad=5) matches jax conv_general_dilated padding=((5,5),(5,5)).
// ---------------------------------------------------------------------------

#define TXW   128      // columns per block
#define HBK   64       // output rows per block
#define RING  20       // ring slots (window span 14 + 4 new writes <= 17, 20 safe)
#define WIMG  512
#define NPLANE 48

#define C1F 0.0001f    // 0.01^2
#define C2F 0.0009f    // 0.03^2

// normalized gaussian, sigma=1.5, 11 taps (computed in double, rounded to fp32)
__device__ __forceinline__ float gw(int k) {
    constexpr float G[11] = {
        0.00102838f, 0.00759876f, 0.03600077f, 0.10936069f, 0.21300553f,
        0.26601172f, 0.21300553f, 0.10936069f, 0.03600077f, 0.00759876f,
        0.00102838f
    };
    return G[k];
}

static __device__ double g_sum;

__global__ void ssim_zero_kernel() { g_sum = 0.0; }

__global__ void ssim_fin_kernel(float* out) {
    out[0] = (float)(1.0 - g_sum * (1.0 / 12582912.0)); // 48*512*512
}

// smem layout (floats):
//   ring[5][RING][TXW]            : 5*20*128 = 12800
//   inb [2][4][144]               : 1152      (row halo buffers, 138 used)
#define RING_FLOATS (5 * RING * TXW)
#define INB_FLOATS  (2 * 4 * 144)
#define SMEM_BYTES  ((RING_FLOATS + INB_FLOATS) * 4)

__global__ __launch_bounds__(128) void ssim_main_kernel(
    const float* __restrict__ img1, const float* __restrict__ img2)
{
    extern __shared__ float sm[];
    float* ring = sm;                  // [5][RING][TXW]
    float* inb  = sm + RING_FLOATS;    // [2][4][144]

    const int tid = threadIdx.x;
    const int b = blockIdx.x;
    const int plane = b >> 5;          // 32 blocks per plane (4 x-strips * 8 y-splits)
    const int t = b & 31;
    const int xbase = (t & 3) * TXW;
    const int yb    = (t >> 2) * HBK;

    const float* p1 = img1 + (size_t)plane * (WIMG * WIMG);
    const float* p2 = img2 + (size_t)plane * (WIMG * WIMG);

    // zero-init ring (keeps discarded-edge reads finite)
    for (int i = tid; i < RING_FLOATS; i += 128) ring[i] = 0.0f;

    // ---- precompute gmem load descriptors: 2 imgs * 4 rows * 138 cols = 1104 ----
    const int NLD = 9; // ceil(1104/128)
    const float* bptr[NLD];
    int   sofs[NLD];
    int   rowv[NLD];
    bool  act[NLD], cval[NLD];
#pragma unroll
    for (int m = 0; m < NLD; m++) {
        int idx = tid + m * 128;
        act[m] = (idx < 1104);
        int im = 0, row = 0, i = 0;
        if (act[m]) {
            im  = idx / 552;  int rem = idx - im * 552;
            row = rem / 138;  i = rem - row * 138;
        }
        int gc = xbase + i - 5;
        cval[m] = act[m] && (gc >= 0) && (gc < WIMG);
        rowv[m] = row;
        sofs[m] = im * (4 * 144) + row * 144 + i;
        const float* base = im ? p2 : p1;
        bptr[m] = base + row * WIMG + (cval[m] ? gc : 0);
    }

    const int hrow = tid >> 5;        // 0..3 (horizontal row within step)
    const int hcg  = tid & 31;        // column group
    const int hx0  = hcg << 2;

    float lsum = 0.0f;

    for (int s = 0; s < 20; ++s) {
        const int r0 = yb - 5 + 4 * s;     // absolute first input row this step

        if (s < 19) {
            // ---- load 4 input rows (with halo, zero-padded) into smem ----
            const long rbase = (long)r0 * WIMG;
#pragma unroll
            for (int m = 0; m < NLD; m++) {
                if (act[m]) {
                    int gr = r0 + rowv[m];
                    float v = 0.0f;
                    if (cval[m] && ((unsigned)gr < (unsigned)WIMG))
                        v = bptr[m][rbase];
                    inb[sofs[m]] = v;
                }
            }
            __syncthreads();

            // ---- horizontal conv: 4 output cols per thread, 1 row ----
            float a[16], bw[16];
            {
                const float4* pa = (const float4*)&inb[hrow * 144 + hx0];
                const float4* pb = (const float4*)&inb[4 * 144 + hrow * 144 + hx0];
#pragma unroll
                for (int m = 0; m < 4; m++) {
                    float4 va = pa[m];
                    a[4*m+0] = va.x; a[4*m+1] = va.y; a[4*m+2] = va.z; a[4*m+3] = va.w;
                    float4 vb = pb[m];
                    bw[4*m+0] = vb.x; bw[4*m+1] = vb.y; bw[4*m+2] = vb.z; bw[4*m+3] = vb.w;
                }
            }
            float acc[5][4];
#pragma unroll
            for (int q = 0; q < 5; q++)
#pragma unroll
                for (int j = 0; j < 4; j++) acc[q][j] = 0.0f;

#pragma unroll
            for (int pos = 0; pos < 14; pos++) {
                float av = a[pos], bv = bw[pos];
                float aa = av * av, b2 = bv * bv, ab = av * bv;
#pragma unroll
                for (int j = 0; j < 4; j++) {
                    int k = pos - j;
                    if (k >= 0 && k <= 10) {
                        float g = gw(k);
                        acc[0][j] = fmaf(av, g, acc[0][j]);
                        acc[1][j] = fmaf(bv, g, acc[1][j]);
                        acc[2][j] = fmaf(aa, g, acc[2][j]);
                        acc[3][j] = fmaf(b2, g, acc[3][j]);
                        acc[4][j] = fmaf(ab, g, acc[4][j]);
                    }
                }
            }
            int wslot = (4 * s + hrow) % RING;
#pragma unroll
            for (int q = 0; q < 5; q++) {
                *(float4*)&ring[(q * RING + wslot) * TXW + hx0] =
                    make_float4(acc[q][0], acc[q][1], acc[q][2], acc[q][3]);
            }
            __syncthreads();
        }

        // ---- vertical conv + SSIM: 1 column (tid), 4 output rows ----
        if (s >= 3) {
            const int wst = 4 * s - 13;             // window start, relative rows
            int slot0 = (wst + 2 * RING) % RING;
            int roff[14];
#pragma unroll
            for (int k = 0; k < 14; k++) {
                int sl = slot0 + k; if (sl >= RING) sl -= RING;
                roff[k] = sl * TXW + tid;
            }
            float sums[5][4];
#pragma unroll
            for (int q = 0; q < 5; q++) {
                const float* rq = ring + q * (RING * TXW);
                float w[14];
#pragma unroll
                for (int k = 0; k < 14; k++) w[k] = rq[roff[k]];
#pragma unroll
                for (int j = 0; j < 4; j++) {
                    float acc = 0.0f;
#pragma unroll
                    for (int k = 0; k < 11; k++) acc = fmaf(w[j + k], gw(k), acc);
                    sums[q][j] = acc;
                }
            }
#pragma unroll
            for (int j = 0; j < 4; j++) {
                int y = yb + wst + j;   // absolute output row
                if (y >= yb && y < yb + HBK) {
                    float mu1 = sums[0][j], mu2 = sums[1][j];
                    float x11 = sums[2][j], x22 = sums[3][j], x12 = sums[4][j];
                    float mu12 = mu1 * mu2;
                    float m1s = mu1 * mu1, m2s = mu2 * mu2;
                    float s1  = x11 - m1s;
                    float s2  = x22 - m2s;
                    float s12 = x12 - mu12;
                    float num = fmaf(2.0f, mu12, C1F) * fmaf(2.0f, s12, C2F);
                    float den = (m1s + m2s + C1F) * (s1 + s2 + C2F);
                    lsum += __fdividef(num, den);
                }
            }
        }
    }

    // ---- reduce: warp shfl -> smem -> one double atomic per block ----
#pragma unroll
    for (int o = 16; o; o >>= 1) lsum += __shfl_xor_sync(0xffffffffu, lsum, o);
    __shared__ float redbuf[4];
    if ((tid & 31) == 0) redbuf[tid >> 5] = lsum;
    __syncthreads();
    if (tid == 0) {
        float bs = redbuf[0] + redbuf[1] + redbuf[2] + redbuf[3];
        atomicAdd(&g_sum, (double)bs);
    }
}

extern "C" void kernel_launch(void* const* d_in, const int* in_sizes, int n_in,
                              void* d_out, int out_size)
{
    const float* img1 = (const float*)d_in[0];
    const float* img2 = (const float*)d_in[1];
    float* out = (float*)d_out;

    cudaFuncSetAttribute(ssim_main_kernel,
                         cudaFuncAttributeMaxDynamicSharedMemorySize, SMEM_BYTES);

    ssim_zero_kernel<<<1, 1>>>();
    ssim_main_kernel<<<NPLANE * 32, 128, SMEM_BYTES>>>(img1, img2);
    ssim_fin_kernel<<<1, 1>>>(out);
}

// round 17
// speedup vs baseline: 1.0134x; 1.0102x over previous
#include <cuda_runtime.h>

// ---------------------------------------------------------------------------
// SSIM loss, fused single-pass implementation.
// imgs: (16,3,512,512) fp32 -> 48 independent 512x512 planes.
// 11x11 gaussian (sigma=1.5) is separable; same kernel for all 5 convs.
// Zero padding (pad=5) matches jax conv_general_dilated padding=((5,5),(5,5)).
// ---------------------------------------------------------------------------

#define TXW   128      // columns per block
#define HBK   64       // output rows per block
#define RING  20       // ring slots (window span 14 + 4 new writes <= 17, 20 safe)
#define WIMG  512
#define NPLANE 48

#define C1F 0.0001f    // 0.01^2
#define C2F 0.0009f    // 0.03^2

// normalized gaussian, sigma=1.5, 11 taps (computed in double, rounded to fp32)
__device__ __forceinline__ float gw(int k) {
    constexpr float G[11] = {
        0.00102838f, 0.00759876f, 0.03600077f, 0.10936069f, 0.21300553f,
        0.26601172f, 0.21300553f, 0.10936069f, 0.03600077f, 0.00759876f,
        0.00102838f
    };
    return G[k];
}

static __device__ double g_sum;

__global__ void ssim_zero_kernel() { g_sum = 0.0; }

__global__ void ssim_fin_kernel(float* out) {
    out[0] = (float)(1.0 - g_sum * (1.0 / 12582912.0)); // 48*512*512
}

// smem layout (floats):
//   ring[5][RING][TXW]            : 5*20*128 = 12800
//   inb [2][4][144]               : 1152      (row halo buffers, 138 used)
#define RING_FLOATS (5 * RING * TXW)
#define INB_FLOATS  (2 * 4 * 144)
#define SMEM_BYTES  ((RING_FLOATS + INB_FLOATS) * 4)

__global__ __launch_bounds__(128) void ssim_main_kernel(
    const float* __restrict__ img1, const float* __restrict__ img2)
{
    extern __shared__ float sm[];
    float* ring = sm;                  // [5][RING][TXW]
    float* inb  = sm + RING_FLOATS;    // [2][4][144]

    const int tid = threadIdx.x;
    const int b = blockIdx.x;
    const int plane = b >> 5;          // 32 blocks per plane (4 x-strips * 8 y-splits)
    const int t = b & 31;
    const int xbase = (t & 3) * TXW;
    const int yb    = (t >> 2) * HBK;

    const float* p1 = img1 + (size_t)plane * (WIMG * WIMG);
    const float* p2 = img2 + (size_t)plane * (WIMG * WIMG);

    // zero-init ring (keeps discarded-edge reads finite)
    for (int i = tid; i < RING_FLOATS; i += 128) ring[i] = 0.0f;

    // ---- precompute gmem load descriptors: 2 imgs * 4 rows * 138 cols = 1104 ----
    const int NLD = 9; // ceil(1104/128)
    const float* bptr[NLD];
    int   sofs[NLD];
    int   rowv[NLD];
    bool  act[NLD], cval[NLD];
#pragma unroll
    for (int m = 0; m < NLD; m++) {
        int idx = tid + m * 128;
        act[m] = (idx < 1104);
        int im = 0, row = 0, i = 0;
        if (act[m]) {
            im  = idx / 552;  int rem = idx - im * 552;
            row = rem / 138;  i = rem - row * 138;
        }
        int gc = xbase + i - 5;
        cval[m] = act[m] && (gc >= 0) && (gc < WIMG);
        rowv[m] = row;
        sofs[m] = im * (4 * 144) + row * 144 + i;
        const float* base = im ? p2 : p1;
        bptr[m] = base + row * WIMG + (cval[m] ? gc : 0);
    }

    const int hrow = tid >> 5;        // 0..3 (horizontal row within step)
    const int hcg  = tid & 31;        // column group
    const int hx0  = hcg << 2;

    float lsum = 0.0f;

    for (int s = 0; s < 20; ++s) {
        const int r0 = yb - 5 + 4 * s;     // absolute first input row this step

        if (s < 19) {
            // ---- load 4 input rows (with halo, zero-padded) into smem ----
            const long rbase = (long)r0 * WIMG;
#pragma unroll
            for (int m = 0; m < NLD; m++) {
                if (act[m]) {
                    int gr = r0 + rowv[m];
                    float v = 0.0f;
                    if (cval[m] && ((unsigned)gr < (unsigned)WIMG))
                        v = bptr[m][rbase];
                    inb[sofs[m]] = v;
                }
            }
            __syncthreads();

            // ---- horizontal conv: 4 output cols per thread, 1 row ----
            float a[16], bw[16];
            {
                const float4* pa = (const float4*)&inb[hrow * 144 + hx0];
                const float4* pb = (const float4*)&inb[4 * 144 + hrow * 144 + hx0];
#pragma unroll
                for (int m = 0; m < 4; m++) {
                    float4 va = pa[m];
                    a[4*m+0] = va.x; a[4*m+1] = va.y; a[4*m+2] = va.z; a[4*m+3] = va.w;
                    float4 vb = pb[m];
                    bw[4*m+0] = vb.x; bw[4*m+1] = vb.y; bw[4*m+2] = vb.z; bw[4*m+3] = vb.w;
                }
            }
            float acc[5][4];
#pragma unroll
            for (int q = 0; q < 5; q++)
#pragma unroll
                for (int j = 0; j < 4; j++) acc[q][j] = 0.0f;

#pragma unroll
            for (int pos = 0; pos < 14; pos++) {
                float av = a[pos], bv = bw[pos];
                float aa = av * av, b2 = bv * bv, ab = av * bv;
#pragma unroll
                for (int j = 0; j < 4; j++) {
                    int k = pos - j;
                    if (k >= 0 && k <= 10) {
                        float g = gw(k);
                        acc[0][j] = fmaf(av, g, acc[0][j]);
                        acc[1][j] = fmaf(bv, g, acc[1][j]);
                        acc[2][j] = fmaf(aa, g, acc[2][j]);
                        acc[3][j] = fmaf(b2, g, acc[3][j]);
                        acc[4][j] = fmaf(ab, g, acc[4][j]);
                    }
                }
            }
            int wslot = (4 * s + hrow) % RING;
#pragma unroll
            for (int q = 0; q < 5; q++) {
                *(float4*)&ring[(q * RING + wslot) * TXW + hx0] =
                    make_float4(acc[q][0], acc[q][1], acc[q][2], acc[q][3]);
            }
            __syncthreads();
        }

        // ---- vertical conv + SSIM: 1 column (tid), 4 output rows ----
        if (s >= 3) {
            const int wst = 4 * s - 13;             // window start, relative rows
            int slot0 = (wst + 2 * RING) % RING;
            int roff[14];
#pragma unroll
            for (int k = 0; k < 14; k++) {
                int sl = slot0 + k; if (sl >= RING) sl -= RING;
                roff[k] = sl * TXW + tid;
            }
            float sums[5][4];
#pragma unroll
            for (int q = 0; q < 5; q++) {
                const float* rq = ring + q * (RING * TXW);
                float w[14];
#pragma unroll
                for (int k = 0; k < 14; k++) w[k] = rq[roff[k]];
#pragma unroll
                for (int j = 0; j < 4; j++) {
                    float acc = 0.0f;
#pragma unroll
                    for (int k = 0; k < 11; k++) acc = fmaf(w[j + k], gw(k), acc);
                    sums[q][j] = acc;
                }
            }
#pragma unroll
            for (int j = 0; j < 4; j++) {
                int y = yb + wst + j;   // absolute output row
                if (y >= yb && y < yb + HBK) {
                    float mu1 = sums[0][j], mu2 = sums[1][j];
                    float x11 = sums[2][j], x22 = sums[3][j], x12 = sums[4][j];
                    float mu12 = mu1 * mu2;
                    float m1s = mu1 * mu1, m2s = mu2 * mu2;
                    float s1  = x11 - m1s;
                    float s2  = x22 - m2s;
                    float s12 = x12 - mu12;
                    float num = fmaf(2.0f, mu12, C1F) * fmaf(2.0f, s12, C2F);
                    float den = (m1s + m2s + C1F) * (s1 + s2 + C2F);
                    lsum += __fdividef(num, den);
                }
            }
        }
    }

    // ---- reduce: warp shfl -> smem -> one double atomic per block ----
#pragma unroll
    for (int o = 16; o; o >>= 1) lsum += __shfl_xor_sync(0xffffffffu, lsum, o);
    __shared__ float redbuf[4];
    if ((tid & 31) == 0) redbuf[tid >> 5] = lsum;
    __syncthreads();
    if (tid == 0) {
        float bs = redbuf[0] + redbuf[1] + redbuf[2] + redbuf[3];
        atomicAdd(&g_sum, (double)bs);
    }
}

extern "C" void kernel_launch(void* const* d_in, const int* in_sizes, int n_in,
                              void* d_out, int out_size)
{
    const float* img1 = (const float*)d_in[0];
    const float* img2 = (const float*)d_in[1];
    float* out = (float*)d_out;

    cudaFuncSetAttribute(ssim_main_kernel,
                         cudaFuncAttributeMaxDynamicSharedMemorySize, SMEM_BYTES);

    ssim_zero_kernel<<<1, 1>>>();
    ssim_main_kernel<<<NPLANE * 32, 128, SMEM_BYTES>>>(img1, img2);
    ssim_fin_kernel<<<1, 1>>>(out);
}